// round 9
// baseline (speedup 1.0000x reference)
#include <cuda_runtime.h>
#include <math.h>

// CPABActivationDifferent: out[n][c] = cpab_transform(x[n][c]; theta[c]).
// Two-level piecewise-affine table (level-1: 4096 bins/ch; invalid bins
// refined x8 in parallel) + compacted iterative fallback for the residual.
// B_BASIS: dgesdd N>>M path => rows 17..31 of Vt come from the LQ
// factorization (dgelq2+dorgl2), reimplemented in fp64.

#define NCELL 16
#define CH 256
#define LROWS 17
#define LCOLS 32
#define NNULL 15
#define KB 4096
#define NSUB 8
#define RCAP (1 << 19)
#define QUEUE_CAP (1 << 25)
#define BUFCAP 16384
#define FNV_P 1099511628211ull
#define FULLM 0xffffffffu

__device__ float2 g_eg[NCELL * CH];   // (eta, 16*gamma)
__device__ float2 g_eu[NCELL * CH];   // (1+ddt*a, 16*ddt*b)
__device__ int    g_flag, g_qcount, g_nref;
struct EndPt { float m, t; unsigned long long h; };
__device__ EndPt  g_ep[CH * (KB + 1)];
__device__ EndPt  g_ep2[RCAP * (NSUB + 1)];
__device__ float2 g_bins[CH * KB];        // valid:(m,t)  invalid:(NaN, idx|-1)
__device__ int    g_reflist[RCAP];        // packed (c<<12)|bin
__device__ float2 g_bins2[RCAP * NSUB];   // refined sub-bins
__device__ int    g_queue[QUEUE_CAP];

__device__ __forceinline__ float decode_time(const void* tptr) {
    int iv = *(const int*)tptr;
    float fv = __int_as_float(iv);
    float af = fabsf(fv);
    if (af >= 1e-6f && af <= 1e6f) return fv;
    return (float)iv;
}
__device__ __forceinline__ double warp_sum(double v) {
    #pragma unroll
    for (int off = 16; off; off >>= 1)
        v += __shfl_xor_sync(FULLM, v, off);
    return v;
}
__device__ __forceinline__ int cell16(float q) { return min((int)q, 15); }

// Exact iterative engine (identical arithmetic to the passing R6 kernel).
__device__ __forceinline__ float cpab_iter(float q, int c,
                                           const float2* __restrict__ eg,
                                           const float2* __restrict__ eu) {
    #pragma unroll 1
    for (int st = 0; st < 10; ++st) {
        int c0 = cell16(q);
        float2 g = eg[(c0 << 8) + c];
        float2 u = eu[(c0 << 8) + c];
        float qc = __fmaf_rn(g.x, q, g.y);
        float qe = __fmaf_rn(u.x, q, u.y);
        #pragma unroll
        for (int ss = 1; ss < 5; ++ss) {
            int cc = cell16(qe);
            float2 v = eu[(cc << 8) + c];
            qe = __fmaf_rn(v.x, qe, v.y);
        }
        q = (cell16(qc) == c0) ? qc : qe;
    }
    return q;
}

// Endpoint evaluation: decision-path hash + composed affine (m,t).
__device__ __forceinline__ EndPt cpab_eval(float q, int c,
                                           const float2* __restrict__ eg,
                                           const float2* __restrict__ eu) {
    unsigned long long h = 1469598103934665603ull;
    float m = 1.0f, t = 0.0f;
    #pragma unroll 1
    for (int st = 0; st < 10; ++st) {
        int c0 = cell16(q);
        float2 g = eg[(c0 << 8) + c];
        float2 u = eu[(c0 << 8) + c];
        float qc = __fmaf_rn(g.x, q, g.y);
        float qe = __fmaf_rn(u.x, q, u.y);
        float A = u.x, B = u.y;
        int cc[4];
        #pragma unroll
        for (int ss = 0; ss < 4; ++ss) {
            cc[ss] = cell16(qe);
            float2 v = eu[(cc[ss] << 8) + c];
            qe = __fmaf_rn(v.x, qe, v.y);
            A  = __fmul_rn(v.x, A);
            B  = __fmaf_rn(v.x, B, v.y);
        }
        int c1 = cell16(qc);
        bool stay = (c1 == c0);
        h = (h ^ (unsigned long long)c0) * FNV_P;
        h = (h ^ (unsigned long long)(c1 + 16)) * FNV_P;
        float am, bm;
        if (stay) { am = g.x; bm = g.y; q = qc; }
        else {
            #pragma unroll
            for (int ss = 0; ss < 4; ++ss)
                h = (h ^ (unsigned long long)(cc[ss] + 32 + 16 * ss)) * FNV_P;
            am = A; bm = B; q = qe;
        }
        m = __fmul_rn(am, m);
        t = __fmaf_rn(am, t, bm);
    }
    EndPt e; e.m = m; e.t = t; e.h = h; return e;
}

__device__ __forceinline__ bool ep_agree(const EndPt& L, const EndPt& R) {
    return (L.h == R.h) &&
           (__float_as_int(L.m) == __float_as_int(R.m)) &&
           (__float_as_int(L.t) == __float_as_int(R.t)) &&
           (L.m > 0.0f);
}

// ---------------------------------------------------------------------------
__global__ void cpab_setup(const float* __restrict__ theta,
                           const void*  __restrict__ timep) {
    __shared__ double sM[LROWS][LCOLS];
    __shared__ double stau[LROWS];
    __shared__ double sQ[NNULL][LCOLS];
    const int tid = threadIdx.x, lane = tid & 31, w = tid >> 5;

    if (tid == 0) { g_qcount = 0; g_nref = 0; g_flag = 1; }

    for (int i = tid; i < LROWS * LCOLS; i += blockDim.x)
        ((double*)sM)[i] = 0.0;
    __syncthreads();
    if (tid == 0) {
        for (int k = 1; k < NCELL; k++) {
            double xk = (double)k / (double)NCELL;
            sM[k - 1][2 * (k - 1)]     =  xk;
            sM[k - 1][2 * (k - 1) + 1] =  1.0;
            sM[k - 1][2 * k]           = -xk;
            sM[k - 1][2 * k + 1]       = -1.0;
        }
        sM[NCELL - 1][1] = 1.0;
        sM[NCELL][2 * NCELL - 2] = 1.0;
        sM[NCELL][2 * NCELL - 1] = 1.0;
    }
    __syncthreads();

    for (int i = 0; i < LROWS; i++) {
        if (w == 0) {
            double aij = sM[i][lane];
            double sq  = (lane > i) ? aij * aij : 0.0;
            sq = warp_sum(sq);
            double alpha = __shfl_sync(FULLM, aij, i);
            double xnorm = sqrt(sq);
            double tau = 0.0;
            if (xnorm != 0.0) {
                double aa = fabs(alpha);
                double wv = fmax(aa, xnorm), zv = fmin(aa, xnorm);
                double r  = (zv == 0.0) ? wv
                            : wv * sqrt(1.0 + (zv / wv) * (zv / wv));
                double beta = (alpha >= 0.0) ? -r : r;
                tau = (beta - alpha) / beta;
                double inv = 1.0 / (alpha - beta);
                if (lane > i)  sM[i][lane] = aij * inv;
                if (lane == i) sM[i][i] = beta;
            }
            if (lane == 0) stau[i] = tau;
        }
        __syncthreads();
        int r = i + 1 + w;
        if (r < LROWS) {
            double tau = stau[i];
            if (tau != 0.0) {
                double v   = (lane == i) ? 1.0
                             : ((lane > i) ? sM[i][lane] : 0.0);
                double arj = (lane >= i) ? sM[r][lane] : 0.0;
                double dot = warp_sum(arj * v);
                if (lane >= i) sM[r][lane] = arj - tau * dot * v;
            }
        }
        __syncthreads();
    }
    if (w < NNULL) {
        int r = LROWS + w;
        double q = (lane == r) ? 1.0 : 0.0;
        for (int i = LROWS - 1; i >= 0; i--) {
            double tau = stau[i];
            double v = (lane == i) ? 1.0 : ((lane > i) ? sM[i][lane] : 0.0);
            double dot = warp_sum(q * v);
            q -= tau * dot * v;
        }
        sQ[w][lane] = q;
    }
    __syncthreads();

    if (tid < CH) {
        const int c = tid;
        float tf  = decode_time(timep);
        float dt  = tf / 10.0f;
        float ddt = dt / 5.0f;
        float A[LCOLS];
        #pragma unroll
        for (int j = 0; j < LCOLS; j++) {
            float s = 0.0f;
            #pragma unroll
            for (int cc = 0; cc < NNULL; cc++)
                s += theta[c * NNULL + cc] * (float)sQ[cc][j];
            A[j] = s;
        }
        bool ok = true;
        #pragma unroll
        for (int k = 0; k < NCELL; k++) {
            float a = A[2 * k], b = A[2 * k + 1];
            float eta, gam;
            if (fabsf(a) > 1e-7f) {
                eta = expf(dt * a);
                gam = __fmul_rn(__fdiv_rn(b, a), __fsub_rn(eta, 1.0f));
            } else { eta = 1.0f; gam = __fmul_rn(b, dt); }
            float ex = __fadd_rn(1.0f, __fmul_rn(ddt, a));
            if (!(ex > 0.0f) || !(eta > 0.0f)) ok = false;
            g_eg[k * CH + c] = make_float2(eta, __fmul_rn(gam, 16.0f));
            g_eu[k * CH + c] = make_float2(ex,
                                           __fmul_rn(__fmul_rn(ddt, b), 16.0f));
        }
        if (!ok) g_flag = 0;
    }
}

// ---------------------------------------------------------------------------
// Level-1 endpoints (global tables -> L1-cached; no smem, full occupancy).
__global__ void __launch_bounds__(512)
cpab_endpoints() {
    const int e = blockIdx.x * blockDim.x + threadIdx.x;
    if (e >= CH * (KB + 1)) return;
    const int c = e / (KB + 1);
    const int j = e - c * (KB + 1);
    g_ep[e] = cpab_eval((float)j * (1.0f / 256.0f), c, g_eg, g_eu);
}

// ---------------------------------------------------------------------------
__global__ void cpab_binbuild() {
    int b = blockIdx.x * blockDim.x + threadIdx.x;
    if (b >= CH * KB) return;
    int c = b >> 12, j = b & (KB - 1);
    EndPt L = g_ep[c * (KB + 1) + j];
    EndPt R = g_ep[c * (KB + 1) + j + 1];
    if (ep_agree(L, R) && g_flag != 0) {
        g_bins[b] = make_float2(L.m, L.t);
    } else {
        int idx = atomicAdd(&g_nref, 1);
        int payload = -1;
        if (idx < RCAP) { g_reflist[idx] = (c << 12) | j; payload = idx; }
        g_bins[b] = make_float2(__int_as_float(0x7fc00000),
                                __int_as_float(payload));
    }
}

// ---------------------------------------------------------------------------
// Parallel refinement: one thread per (refined bin, sub-endpoint) eval.
__global__ void __launch_bounds__(512)
cpab_refine_eval() {
    const int nref = min(g_nref, RCAP);
    const long long total = (long long)nref * (NSUB + 1);
    const long long stride = (long long)gridDim.x * blockDim.x;
    for (long long t = (long long)blockIdx.x * blockDim.x + threadIdx.x;
         t < total; t += stride) {
        int r = (int)(t / (NSUB + 1));
        int s = (int)(t - (long long)r * (NSUB + 1));
        int cbv = g_reflist[r];
        int c = cbv >> 12, b = cbv & (KB - 1);
        g_ep2[r * (NSUB + 1) + s] =
            cpab_eval((float)(b * NSUB + s) * (1.0f / 2048.0f), c, g_eg, g_eu);
    }
}

__global__ void __launch_bounds__(512)
cpab_binbuild2() {
    const int nref = min(g_nref, RCAP);
    const long long total = (long long)nref * NSUB;
    const long long stride = (long long)gridDim.x * blockDim.x;
    const int flag = g_flag;
    for (long long t = (long long)blockIdx.x * blockDim.x + threadIdx.x;
         t < total; t += stride) {
        int r = (int)(t >> 3);
        int s = (int)(t & (NSUB - 1));
        EndPt L = g_ep2[r * (NSUB + 1) + s];
        EndPt R = g_ep2[r * (NSUB + 1) + s + 1];
        g_bins2[r * NSUB + s] =
            (ep_agree(L, R) && flag != 0)
                ? make_float2(L.m, L.t)
                : make_float2(__int_as_float(0x7fc00000), 0.0f);
    }
}

// ---------------------------------------------------------------------------
// Pass 1: float4, MLP-first gathers (4x lvl-1 then 4x lvl-2 in flight),
// one warp-scan-aggregated queue push per float4.
// ---------------------------------------------------------------------------
__global__ void __launch_bounds__(512, 2)
cpab_pass1(const float4* __restrict__ x4, const float* __restrict__ x,
           const float* __restrict__ theta, float4* __restrict__ out4,
           float* __restrict__ out, int n4, long long n, int ntheta) {
    extern __shared__ int s_buf[];
    __shared__ int s_cnt, s_base;
    if (threadIdx.x == 0) s_cnt = 0;
    __syncthreads();

    const int lane = threadIdx.x & 31;
    const int stride = gridDim.x * blockDim.x;
    const int gtid = blockIdx.x * blockDim.x + threadIdx.x;

    for (int t = gtid; t < ntheta; t += stride)
        out[n + t] = theta[t];

    const int rem = (int)(n - (long long)n4 * 4);
    if (blockIdx.x == 0) {
        for (int t = threadIdx.x; t < rem; t += blockDim.x) {
            long long i = (long long)n4 * 4 + t;
            float xv = x[i];
            float s = __fmaf_rn(xv, 1.0f / 6.0f, 0.5f);
            if (s >= 1.0f || s <= 0.0f) { out[i] = xv; continue; }
            float r = cpab_iter(__fmul_rn(s, 16.0f), (int)(i & (CH - 1)),
                                g_eg, g_eu);
            out[i] = __fmaf_rn(r, 0.375f, -3.0f);
        }
    }

    int i4 = gtid;
    while (true) {
        bool act = (i4 < n4);
        if (!__any_sync(FULLM, act)) break;
        float4 xv = act ? __ldg(x4 + i4) : make_float4(9e9f, 9e9f, 9e9f, 9e9f);
        const int cb = (i4 << 2) & (CH - 1);
        const float* xp = &xv.x;

        float qv[4]; int bin[4]; bool ood[4];
        #pragma unroll
        for (int j = 0; j < 4; ++j) {
            float s = __fmaf_rn(xp[j], 1.0f / 6.0f, 0.5f);
            ood[j] = (s >= 1.0f) || (s <= 0.0f);
            qv[j] = ood[j] ? 8.0f : __fmul_rn(s, 16.0f);
            bin[j] = min((int)__fmul_rn(qv[j], 256.0f), KB - 1);
        }
        // 4 independent level-1 gathers in flight
        float2 mt[4];
        #pragma unroll
        for (int j = 0; j < 4; ++j)
            mt[j] = __ldg(&g_bins[((cb + j) << 12) + bin[j]]);
        // 4 level-2 gathers (broadcast addr 0 for valid slots: ~free)
        int a2[4];
        #pragma unroll
        for (int j = 0; j < 4; ++j) {
            bool nan1 = !(mt[j].x == mt[j].x);
            int idx = __float_as_int(mt[j].y);
            int sub = min(max((int)__fmul_rn(qv[j], 2048.0f)
                              - (bin[j] << 3), 0), NSUB - 1);
            a2[j] = (nan1 && idx >= 0) ? idx * NSUB + sub : 0;
        }
        float2 m2[4];
        #pragma unroll
        for (int j = 0; j < 4; ++j)
            m2[j] = __ldg(&g_bins2[a2[j]]);

        float res[4];
        int cnt = 0;
        int slot[4];
        #pragma unroll
        for (int j = 0; j < 4; ++j) {
            bool nan1 = !(mt[j].x == mt[j].x);
            bool nan2 = !(m2[j].x == m2[j].x);
            int idx = __float_as_int(mt[j].y);
            float2 use = nan1 ? m2[j] : mt[j];
            bool bad = nan1 && (idx < 0 || nan2);
            res[j] = ood[j] ? xp[j]
                     : __fmaf_rn(__fmaf_rn(use.x, qv[j], use.y), 0.375f, -3.0f);
            if (bad && !ood[j] && act) { slot[cnt] = j; cnt++; }
        }

        // warp-aggregated queue push: one smem atomic per warp per float4
        if (__ballot_sync(FULLM, cnt > 0)) {
            int pre = cnt;
            #pragma unroll
            for (int off = 1; off < 32; off <<= 1) {
                int tv = __shfl_up_sync(FULLM, pre, off);
                if (lane >= off) pre += tv;
            }
            int tot = __shfl_sync(FULLM, pre, 31);
            int ex = pre - cnt;
            int basev = 0;
            if (lane == 0) basev = atomicAdd(&s_cnt, tot);
            basev = __shfl_sync(FULLM, basev, 0);
            for (int k = 0; k < cnt; ++k) {
                int j = slot[k];
                int pos = basev + ex + k;
                if (pos < BUFCAP) {
                    s_buf[pos] = (i4 << 2) + j;
                    res[j] = 0.0f;               // pass2 overwrites
                } else {                          // overflow valve: exact path
                    res[j] = __fmaf_rn(cpab_iter(qv[j], cb + j, g_eg, g_eu),
                                       0.375f, -3.0f);
                }
            }
        }

        if (act) out4[i4] = make_float4(res[0], res[1], res[2], res[3]);
        i4 += stride;
    }

    __syncthreads();
    int cnt = min(s_cnt, BUFCAP);
    if (threadIdx.x == 0) s_base = atomicAdd(&g_qcount, cnt);
    __syncthreads();
    int base = s_base;
    for (int k = threadIdx.x; k < cnt; k += blockDim.x)
        g_queue[base + k] = s_buf[k];
}

// ---------------------------------------------------------------------------
__global__ void __launch_bounds__(512, 3)
cpab_pass2(const float* __restrict__ x, float* __restrict__ out) {
    __shared__ float2 s_eg[NCELL * CH], s_eu[NCELL * CH];
    for (int i = threadIdx.x; i < NCELL * CH; i += blockDim.x) {
        s_eg[i] = g_eg[i]; s_eu[i] = g_eu[i];
    }
    __syncthreads();
    const int total = g_qcount;
    const int stride = gridDim.x * blockDim.x;
    for (int t = blockIdx.x * blockDim.x + threadIdx.x; t < total; t += stride) {
        int i = g_queue[t];
        float xv = __ldg(x + i);
        float s = __fmaf_rn(xv, 1.0f / 6.0f, 0.5f);
        float q = __fmul_rn(s, 16.0f);
        float r = cpab_iter(q, i & (CH - 1), s_eg, s_eu);
        out[i] = __fmaf_rn(r, 0.375f, -3.0f);
    }
}

extern "C" void kernel_launch(void* const* d_in, const int* in_sizes, int n_in,
                              void* d_out, int out_size) {
    const float* x     = (const float*)d_in[0];
    const void*  timep = d_in[4];
    const float* theta = (const float*)d_in[5];
    float* out = (float*)d_out;

    const long long n = (long long)in_sizes[0];
    const int ntheta = out_size - (int)n;
    const int n4 = (int)(n >> 2);

    cpab_setup<<<1, 512>>>(theta, timep);
    cpab_endpoints<<<(CH * (KB + 1) + 511) / 512, 512>>>();
    cpab_binbuild<<<(CH * KB) / 512, 512>>>();
    cpab_refine_eval<<<912, 512>>>();
    cpab_binbuild2<<<912, 512>>>();

    cudaFuncSetAttribute(cpab_pass1,
                         cudaFuncAttributeMaxDynamicSharedMemorySize,
                         BUFCAP * (int)sizeof(int));
    cpab_pass1<<<456, 512, BUFCAP * sizeof(int)>>>(
        (const float4*)x, x, theta, (float4*)out, out, n4, n, ntheta);
    cpab_pass2<<<304, 512>>>(x, out);
}

// round 10
// speedup vs baseline: 1.8289x; 1.8289x over previous
#include <cuda_runtime.h>
#include <math.h>

// CPABActivationDifferent: out[n][c] = cpab_transform(x[n][c]; theta[c]).
// Two-level piecewise-affine table (level-1: 4096 bins/ch; invalid bins
// refined x8 in parallel) + compacted iterative fallback for the ~4% residual.
// B_BASIS: dgesdd N>>M path => rows 17..31 of Vt come from the LQ
// factorization (dgelq2+dorgl2), reimplemented in fp64.
//
// R10 = composition of measured-best components: R7 scalar pass1 (200us at
// 25% invalid; now ~4% invalid) + 2-level lookup, R8 smem endpoints, R9
// parallel refine, R8 pass2. No dynamically-indexed local arrays anywhere.

#define NCELL 16
#define CH 256
#define LROWS 17
#define LCOLS 32
#define NNULL 15
#define KB 4096
#define NSUB 8
#define RCAP (1 << 19)
#define QUEUE_CAP (1 << 25)
#define BUFCAP 16384
#define FNV_P 1099511628211ull
#define FULLM 0xffffffffu

__device__ float2 g_eg[NCELL * CH];   // (eta, 16*gamma)
__device__ float2 g_eu[NCELL * CH];   // (1+ddt*a, 16*ddt*b)
__device__ int    g_flag, g_qcount, g_nref;
struct EndPt { float m, t; unsigned long long h; };
__device__ EndPt  g_ep[CH * (KB + 1)];
__device__ EndPt  g_ep2[RCAP * (NSUB + 1)];
__device__ float2 g_bins[CH * KB];        // valid:(m,t)  invalid:(NaN, idx|-1)
__device__ int    g_reflist[RCAP];        // packed (c<<12)|bin
__device__ float2 g_bins2[RCAP * NSUB];   // refined sub-bins
__device__ int    g_queue[QUEUE_CAP];

__device__ __forceinline__ float decode_time(const void* tptr) {
    int iv = *(const int*)tptr;
    float fv = __int_as_float(iv);
    float af = fabsf(fv);
    if (af >= 1e-6f && af <= 1e6f) return fv;
    return (float)iv;
}
__device__ __forceinline__ double warp_sum(double v) {
    #pragma unroll
    for (int off = 16; off; off >>= 1)
        v += __shfl_xor_sync(FULLM, v, off);
    return v;
}
__device__ __forceinline__ int cell16(float q) { return min((int)q, 15); }

// Exact iterative engine (identical arithmetic to the passing R6 kernel).
__device__ __forceinline__ float cpab_iter(float q, int c,
                                           const float2* __restrict__ eg,
                                           const float2* __restrict__ eu) {
    #pragma unroll 1
    for (int st = 0; st < 10; ++st) {
        int c0 = cell16(q);
        float2 g = eg[(c0 << 8) + c];
        float2 u = eu[(c0 << 8) + c];
        float qc = __fmaf_rn(g.x, q, g.y);
        float qe = __fmaf_rn(u.x, q, u.y);
        #pragma unroll
        for (int ss = 1; ss < 5; ++ss) {
            int cc = cell16(qe);
            float2 v = eu[(cc << 8) + c];
            qe = __fmaf_rn(v.x, qe, v.y);
        }
        q = (cell16(qc) == c0) ? qc : qe;
    }
    return q;
}

// Endpoint evaluation: decision-path hash + composed affine (m,t).
__device__ __forceinline__ EndPt cpab_eval(float q, int c,
                                           const float2* __restrict__ eg,
                                           const float2* __restrict__ eu) {
    unsigned long long h = 1469598103934665603ull;
    float m = 1.0f, t = 0.0f;
    #pragma unroll 1
    for (int st = 0; st < 10; ++st) {
        int c0 = cell16(q);
        float2 g = eg[(c0 << 8) + c];
        float2 u = eu[(c0 << 8) + c];
        float qc = __fmaf_rn(g.x, q, g.y);
        float qe = __fmaf_rn(u.x, q, u.y);
        float A = u.x, B = u.y;
        int cc[4];
        #pragma unroll
        for (int ss = 0; ss < 4; ++ss) {
            cc[ss] = cell16(qe);
            float2 v = eu[(cc[ss] << 8) + c];
            qe = __fmaf_rn(v.x, qe, v.y);
            A  = __fmul_rn(v.x, A);
            B  = __fmaf_rn(v.x, B, v.y);
        }
        int c1 = cell16(qc);
        bool stay = (c1 == c0);
        h = (h ^ (unsigned long long)c0) * FNV_P;
        h = (h ^ (unsigned long long)(c1 + 16)) * FNV_P;
        float am, bm;
        if (stay) { am = g.x; bm = g.y; q = qc; }
        else {
            #pragma unroll
            for (int ss = 0; ss < 4; ++ss)
                h = (h ^ (unsigned long long)(cc[ss] + 32 + 16 * ss)) * FNV_P;
            am = A; bm = B; q = qe;
        }
        m = __fmul_rn(am, m);
        t = __fmaf_rn(am, t, bm);
    }
    EndPt e; e.m = m; e.t = t; e.h = h; return e;
}

__device__ __forceinline__ bool ep_agree(const EndPt& L, const EndPt& R) {
    return (L.h == R.h) &&
           (__float_as_int(L.m) == __float_as_int(R.m)) &&
           (__float_as_int(L.t) == __float_as_int(R.t)) &&
           (L.m > 0.0f);
}

// ---------------------------------------------------------------------------
__global__ void cpab_setup(const float* __restrict__ theta,
                           const void*  __restrict__ timep) {
    __shared__ double sM[LROWS][LCOLS];
    __shared__ double stau[LROWS];
    __shared__ double sQ[NNULL][LCOLS];
    const int tid = threadIdx.x, lane = tid & 31, w = tid >> 5;

    if (tid == 0) { g_qcount = 0; g_nref = 0; g_flag = 1; }

    for (int i = tid; i < LROWS * LCOLS; i += blockDim.x)
        ((double*)sM)[i] = 0.0;
    __syncthreads();
    if (tid == 0) {
        for (int k = 1; k < NCELL; k++) {
            double xk = (double)k / (double)NCELL;
            sM[k - 1][2 * (k - 1)]     =  xk;
            sM[k - 1][2 * (k - 1) + 1] =  1.0;
            sM[k - 1][2 * k]           = -xk;
            sM[k - 1][2 * k + 1]       = -1.0;
        }
        sM[NCELL - 1][1] = 1.0;
        sM[NCELL][2 * NCELL - 2] = 1.0;
        sM[NCELL][2 * NCELL - 1] = 1.0;
    }
    __syncthreads();

    for (int i = 0; i < LROWS; i++) {
        if (w == 0) {
            double aij = sM[i][lane];
            double sq  = (lane > i) ? aij * aij : 0.0;
            sq = warp_sum(sq);
            double alpha = __shfl_sync(FULLM, aij, i);
            double xnorm = sqrt(sq);
            double tau = 0.0;
            if (xnorm != 0.0) {
                double aa = fabs(alpha);
                double wv = fmax(aa, xnorm), zv = fmin(aa, xnorm);
                double r  = (zv == 0.0) ? wv
                            : wv * sqrt(1.0 + (zv / wv) * (zv / wv));
                double beta = (alpha >= 0.0) ? -r : r;
                tau = (beta - alpha) / beta;
                double inv = 1.0 / (alpha - beta);
                if (lane > i)  sM[i][lane] = aij * inv;
                if (lane == i) sM[i][i] = beta;
            }
            if (lane == 0) stau[i] = tau;
        }
        __syncthreads();
        int r = i + 1 + w;
        if (r < LROWS) {
            double tau = stau[i];
            if (tau != 0.0) {
                double v   = (lane == i) ? 1.0
                             : ((lane > i) ? sM[i][lane] : 0.0);
                double arj = (lane >= i) ? sM[r][lane] : 0.0;
                double dot = warp_sum(arj * v);
                if (lane >= i) sM[r][lane] = arj - tau * dot * v;
            }
        }
        __syncthreads();
    }
    if (w < NNULL) {
        int r = LROWS + w;
        double q = (lane == r) ? 1.0 : 0.0;
        for (int i = LROWS - 1; i >= 0; i--) {
            double tau = stau[i];
            double v = (lane == i) ? 1.0 : ((lane > i) ? sM[i][lane] : 0.0);
            double dot = warp_sum(q * v);
            q -= tau * dot * v;
        }
        sQ[w][lane] = q;
    }
    __syncthreads();

    if (tid < CH) {
        const int c = tid;
        float tf  = decode_time(timep);
        float dt  = tf / 10.0f;
        float ddt = dt / 5.0f;
        float A[LCOLS];
        #pragma unroll
        for (int j = 0; j < LCOLS; j++) {
            float s = 0.0f;
            #pragma unroll
            for (int cc = 0; cc < NNULL; cc++)
                s += theta[c * NNULL + cc] * (float)sQ[cc][j];
            A[j] = s;
        }
        bool ok = true;
        #pragma unroll
        for (int k = 0; k < NCELL; k++) {
            float a = A[2 * k], b = A[2 * k + 1];
            float eta, gam;
            if (fabsf(a) > 1e-7f) {
                eta = expf(dt * a);
                gam = __fmul_rn(__fdiv_rn(b, a), __fsub_rn(eta, 1.0f));
            } else { eta = 1.0f; gam = __fmul_rn(b, dt); }
            float ex = __fadd_rn(1.0f, __fmul_rn(ddt, a));
            if (!(ex > 0.0f) || !(eta > 0.0f)) ok = false;
            g_eg[k * CH + c] = make_float2(eta, __fmul_rn(gam, 16.0f));
            g_eu[k * CH + c] = make_float2(ex,
                                           __fmul_rn(__fmul_rn(ddt, b), 16.0f));
        }
        if (!ok) g_flag = 0;
    }
}

// ---------------------------------------------------------------------------
// Level-1 endpoints (smem tables — measured-good R8 version).
__global__ void __launch_bounds__(512)
cpab_endpoints() {
    __shared__ float2 s_eg[NCELL * CH], s_eu[NCELL * CH];
    for (int i = threadIdx.x; i < NCELL * CH; i += blockDim.x) {
        s_eg[i] = g_eg[i]; s_eu[i] = g_eu[i];
    }
    __syncthreads();
    const int e = blockIdx.x * blockDim.x + threadIdx.x;
    if (e >= CH * (KB + 1)) return;
    const int c = e / (KB + 1);
    const int j = e - c * (KB + 1);
    g_ep[e] = cpab_eval((float)j * (1.0f / 256.0f), c, s_eg, s_eu);
}

// ---------------------------------------------------------------------------
__global__ void cpab_binbuild() {
    int b = blockIdx.x * blockDim.x + threadIdx.x;
    if (b >= CH * KB) return;
    int c = b >> 12, j = b & (KB - 1);
    EndPt L = g_ep[c * (KB + 1) + j];
    EndPt R = g_ep[c * (KB + 1) + j + 1];
    if (ep_agree(L, R) && g_flag != 0) {
        g_bins[b] = make_float2(L.m, L.t);
    } else {
        int idx = atomicAdd(&g_nref, 1);
        int payload = -1;
        if (idx < RCAP) { g_reflist[idx] = (c << 12) | j; payload = idx; }
        g_bins[b] = make_float2(__int_as_float(0x7fc00000),
                                __int_as_float(payload));
    }
}

// ---------------------------------------------------------------------------
// Parallel refinement: one thread per (refined bin, sub-endpoint) eval.
// Adjacent threads share (c, bin) => warp-coherent table access (R9-measured).
__global__ void __launch_bounds__(512)
cpab_refine_eval() {
    const int nref = min(g_nref, RCAP);
    const long long total = (long long)nref * (NSUB + 1);
    const long long stride = (long long)gridDim.x * blockDim.x;
    for (long long t = (long long)blockIdx.x * blockDim.x + threadIdx.x;
         t < total; t += stride) {
        int r = (int)(t / (NSUB + 1));
        int s = (int)(t - (long long)r * (NSUB + 1));
        int cbv = g_reflist[r];
        int c = cbv >> 12, b = cbv & (KB - 1);
        g_ep2[r * (NSUB + 1) + s] =
            cpab_eval((float)(b * NSUB + s) * (1.0f / 2048.0f), c, g_eg, g_eu);
    }
}

__global__ void __launch_bounds__(512)
cpab_binbuild2() {
    const int nref = min(g_nref, RCAP);
    const long long total = (long long)nref * NSUB;
    const long long stride = (long long)gridDim.x * blockDim.x;
    const int flag = g_flag;
    for (long long t = (long long)blockIdx.x * blockDim.x + threadIdx.x;
         t < total; t += stride) {
        int r = (int)(t >> 3);
        int s = (int)(t & (NSUB - 1));
        EndPt L = g_ep2[r * (NSUB + 1) + s];
        EndPt R = g_ep2[r * (NSUB + 1) + s + 1];
        g_bins2[r * NSUB + s] =
            (ep_agree(L, R) && flag != 0)
                ? make_float2(L.m, L.t)
                : make_float2(__int_as_float(0x7fc00000), 0.0f);
    }
}

// ---------------------------------------------------------------------------
// Pass 1: R7-measured scalar structure + two-level lookup. Invalid fraction
// is ~4% so the simple per-lane smem atomic push is cheap. No local arrays.
// ---------------------------------------------------------------------------
__global__ void __launch_bounds__(512, 3)
cpab_pass1(const float* __restrict__ x, const float* __restrict__ theta,
           float* __restrict__ out, int n, int ntheta) {
    extern __shared__ int s_buf[];
    __shared__ int s_cnt, s_base;
    if (threadIdx.x == 0) s_cnt = 0;
    __syncthreads();

    const int stride = gridDim.x * blockDim.x;
    const int i0 = blockIdx.x * blockDim.x + threadIdx.x;

    for (int t = i0; t < ntheta; t += stride)
        out[n + t] = theta[t];

    for (int i = i0; i < n; i += stride) {
        float xv = __ldg(x + i);
        float s = __fmaf_rn(xv, 1.0f / 6.0f, 0.5f);
        if (s >= 1.0f || s <= 0.0f) { out[i] = xv; continue; }
        float q = __fmul_rn(s, 16.0f);
        int bin = min((int)__fmul_rn(q, 256.0f), KB - 1);
        int c = i & (CH - 1);
        float2 mt = __ldg(&g_bins[(c << 12) + bin]);
        bool resolved = (mt.x == mt.x);           // level-1 valid
        if (!resolved) {
            int idx = __float_as_int(mt.y);
            if (idx >= 0) {
                int sub = min(max((int)__fmul_rn(q, 2048.0f) - (bin << 3), 0),
                              NSUB - 1);
                float2 m2 = __ldg(&g_bins2[idx * NSUB + sub]);
                if (m2.x == m2.x) { mt = m2; resolved = true; }
            }
        }
        if (resolved) {
            out[i] = __fmaf_rn(__fmaf_rn(mt.x, q, mt.y), 0.375f, -3.0f);
        } else {
            int pos = atomicAdd(&s_cnt, 1);
            if (pos < BUFCAP) {
                s_buf[pos] = i;                   // pass2 overwrites out[i]
            } else {                              // overflow valve: exact path
                out[i] = __fmaf_rn(cpab_iter(q, c, g_eg, g_eu),
                                   0.375f, -3.0f);
            }
        }
    }
    __syncthreads();
    int cnt = min(s_cnt, BUFCAP);
    if (threadIdx.x == 0) s_base = atomicAdd(&g_qcount, cnt);
    __syncthreads();
    int base = s_base;
    for (int k = threadIdx.x; k < cnt; k += blockDim.x)
        g_queue[base + k] = s_buf[k];
}

// ---------------------------------------------------------------------------
__global__ void __launch_bounds__(512, 3)
cpab_pass2(const float* __restrict__ x, float* __restrict__ out) {
    __shared__ float2 s_eg[NCELL * CH], s_eu[NCELL * CH];
    for (int i = threadIdx.x; i < NCELL * CH; i += blockDim.x) {
        s_eg[i] = g_eg[i]; s_eu[i] = g_eu[i];
    }
    __syncthreads();
    const int total = g_qcount;
    const int stride = gridDim.x * blockDim.x;
    for (int t = blockIdx.x * blockDim.x + threadIdx.x; t < total; t += stride) {
        int i = g_queue[t];
        float xv = __ldg(x + i);
        float s = __fmaf_rn(xv, 1.0f / 6.0f, 0.5f);
        float q = __fmul_rn(s, 16.0f);
        float r = cpab_iter(q, i & (CH - 1), s_eg, s_eu);
        out[i] = __fmaf_rn(r, 0.375f, -3.0f);
    }
}

extern "C" void kernel_launch(void* const* d_in, const int* in_sizes, int n_in,
                              void* d_out, int out_size) {
    const float* x     = (const float*)d_in[0];
    const void*  timep = d_in[4];
    const float* theta = (const float*)d_in[5];
    float* out = (float*)d_out;

    const int n = in_sizes[0];
    const int ntheta = out_size - n;

    cpab_setup<<<1, 512>>>(theta, timep);
    cpab_endpoints<<<(CH * (KB + 1) + 511) / 512, 512>>>();
    cpab_binbuild<<<(CH * KB) / 512, 512>>>();
    cpab_refine_eval<<<912, 512>>>();
    cpab_binbuild2<<<912, 512>>>();

    cudaFuncSetAttribute(cpab_pass1,
                         cudaFuncAttributeMaxDynamicSharedMemorySize,
                         BUFCAP * (int)sizeof(int));
    cpab_pass1<<<456, 512, BUFCAP * sizeof(int)>>>(x, theta, out, n, ntheta);
    cpab_pass2<<<304, 512>>>(x, out);
}

// round 11
// speedup vs baseline: 1.8554x; 1.0145x over previous
#include <cuda_runtime.h>
#include <math.h>

// CPABActivationDifferent: out[n][c] = cpab_transform(x[n][c]; theta[c]).
// Two-level piecewise-affine table + compacted iterative fallback.
// B_BASIS: dgesdd N>>M path => rows 17..31 of Vt come from the LQ
// factorization (dgelq2+dorgl2), reimplemented in fp64.
//
// R11 = R10 with pass1 rebuilt for MLP: 4 elements per thread (float4),
// all lane state in MANUAL SCALARS (macros, no dynamically-indexed local
// arrays => no LMEM, the R9 failure), 4 level-1 gathers then 4 level-2
// gathers in flight, per-lane atomic push for the ~4% residual.

#define NCELL 16
#define CH 256
#define LROWS 17
#define LCOLS 32
#define NNULL 15
#define KB 4096
#define NSUB 8
#define RCAP (1 << 19)
#define QUEUE_CAP (1 << 25)
#define BUFCAP 16384
#define FNV_P 1099511628211ull
#define FULLM 0xffffffffu

__device__ float2 g_eg[NCELL * CH];   // (eta, 16*gamma)
__device__ float2 g_eu[NCELL * CH];   // (1+ddt*a, 16*ddt*b)
__device__ int    g_flag, g_qcount, g_nref;
struct EndPt { float m, t; unsigned long long h; };
__device__ EndPt  g_ep[CH * (KB + 1)];
__device__ EndPt  g_ep2[RCAP * (NSUB + 1)];
__device__ float2 g_bins[CH * KB];        // valid:(m,t)  invalid:(NaN, idx|-1)
__device__ int    g_reflist[RCAP];        // packed (c<<12)|bin
__device__ float2 g_bins2[RCAP * NSUB];   // refined sub-bins
__device__ int    g_queue[QUEUE_CAP];

__device__ __forceinline__ float decode_time(const void* tptr) {
    int iv = *(const int*)tptr;
    float fv = __int_as_float(iv);
    float af = fabsf(fv);
    if (af >= 1e-6f && af <= 1e6f) return fv;
    return (float)iv;
}
__device__ __forceinline__ double warp_sum(double v) {
    #pragma unroll
    for (int off = 16; off; off >>= 1)
        v += __shfl_xor_sync(FULLM, v, off);
    return v;
}
__device__ __forceinline__ int cell16(float q) { return min((int)q, 15); }

// Exact iterative engine (identical arithmetic to the passing R6 kernel).
__device__ __forceinline__ float cpab_iter(float q, int c,
                                           const float2* __restrict__ eg,
                                           const float2* __restrict__ eu) {
    #pragma unroll 1
    for (int st = 0; st < 10; ++st) {
        int c0 = cell16(q);
        float2 g = eg[(c0 << 8) + c];
        float2 u = eu[(c0 << 8) + c];
        float qc = __fmaf_rn(g.x, q, g.y);
        float qe = __fmaf_rn(u.x, q, u.y);
        #pragma unroll
        for (int ss = 1; ss < 5; ++ss) {
            int cc = cell16(qe);
            float2 v = eu[(cc << 8) + c];
            qe = __fmaf_rn(v.x, qe, v.y);
        }
        q = (cell16(qc) == c0) ? qc : qe;
    }
    return q;
}

// Endpoint evaluation: decision-path hash + composed affine (m,t).
__device__ __forceinline__ EndPt cpab_eval(float q, int c,
                                           const float2* __restrict__ eg,
                                           const float2* __restrict__ eu) {
    unsigned long long h = 1469598103934665603ull;
    float m = 1.0f, t = 0.0f;
    #pragma unroll 1
    for (int st = 0; st < 10; ++st) {
        int c0 = cell16(q);
        float2 g = eg[(c0 << 8) + c];
        float2 u = eu[(c0 << 8) + c];
        float qc = __fmaf_rn(g.x, q, g.y);
        float qe = __fmaf_rn(u.x, q, u.y);
        float A = u.x, B = u.y;
        int cc[4];
        #pragma unroll
        for (int ss = 0; ss < 4; ++ss) {
            cc[ss] = cell16(qe);
            float2 v = eu[(cc[ss] << 8) + c];
            qe = __fmaf_rn(v.x, qe, v.y);
            A  = __fmul_rn(v.x, A);
            B  = __fmaf_rn(v.x, B, v.y);
        }
        int c1 = cell16(qc);
        bool stay = (c1 == c0);
        h = (h ^ (unsigned long long)c0) * FNV_P;
        h = (h ^ (unsigned long long)(c1 + 16)) * FNV_P;
        float am, bm;
        if (stay) { am = g.x; bm = g.y; q = qc; }
        else {
            #pragma unroll
            for (int ss = 0; ss < 4; ++ss)
                h = (h ^ (unsigned long long)(cc[ss] + 32 + 16 * ss)) * FNV_P;
            am = A; bm = B; q = qe;
        }
        m = __fmul_rn(am, m);
        t = __fmaf_rn(am, t, bm);
    }
    EndPt e; e.m = m; e.t = t; e.h = h; return e;
}

__device__ __forceinline__ bool ep_agree(const EndPt& L, const EndPt& R) {
    return (L.h == R.h) &&
           (__float_as_int(L.m) == __float_as_int(R.m)) &&
           (__float_as_int(L.t) == __float_as_int(R.t)) &&
           (L.m > 0.0f);
}

// ---------------------------------------------------------------------------
__global__ void cpab_setup(const float* __restrict__ theta,
                           const void*  __restrict__ timep) {
    __shared__ double sM[LROWS][LCOLS];
    __shared__ double stau[LROWS];
    __shared__ double sQ[NNULL][LCOLS];
    const int tid = threadIdx.x, lane = tid & 31, w = tid >> 5;

    if (tid == 0) { g_qcount = 0; g_nref = 0; g_flag = 1; }

    for (int i = tid; i < LROWS * LCOLS; i += blockDim.x)
        ((double*)sM)[i] = 0.0;
    __syncthreads();
    if (tid == 0) {
        for (int k = 1; k < NCELL; k++) {
            double xk = (double)k / (double)NCELL;
            sM[k - 1][2 * (k - 1)]     =  xk;
            sM[k - 1][2 * (k - 1) + 1] =  1.0;
            sM[k - 1][2 * k]           = -xk;
            sM[k - 1][2 * k + 1]       = -1.0;
        }
        sM[NCELL - 1][1] = 1.0;
        sM[NCELL][2 * NCELL - 2] = 1.0;
        sM[NCELL][2 * NCELL - 1] = 1.0;
    }
    __syncthreads();

    for (int i = 0; i < LROWS; i++) {
        if (w == 0) {
            double aij = sM[i][lane];
            double sq  = (lane > i) ? aij * aij : 0.0;
            sq = warp_sum(sq);
            double alpha = __shfl_sync(FULLM, aij, i);
            double xnorm = sqrt(sq);
            double tau = 0.0;
            if (xnorm != 0.0) {
                double aa = fabs(alpha);
                double wv = fmax(aa, xnorm), zv = fmin(aa, xnorm);
                double r  = (zv == 0.0) ? wv
                            : wv * sqrt(1.0 + (zv / wv) * (zv / wv));
                double beta = (alpha >= 0.0) ? -r : r;
                tau = (beta - alpha) / beta;
                double inv = 1.0 / (alpha - beta);
                if (lane > i)  sM[i][lane] = aij * inv;
                if (lane == i) sM[i][i] = beta;
            }
            if (lane == 0) stau[i] = tau;
        }
        __syncthreads();
        int r = i + 1 + w;
        if (r < LROWS) {
            double tau = stau[i];
            if (tau != 0.0) {
                double v   = (lane == i) ? 1.0
                             : ((lane > i) ? sM[i][lane] : 0.0);
                double arj = (lane >= i) ? sM[r][lane] : 0.0;
                double dot = warp_sum(arj * v);
                if (lane >= i) sM[r][lane] = arj - tau * dot * v;
            }
        }
        __syncthreads();
    }
    if (w < NNULL) {
        int r = LROWS + w;
        double q = (lane == r) ? 1.0 : 0.0;
        for (int i = LROWS - 1; i >= 0; i--) {
            double tau = stau[i];
            double v = (lane == i) ? 1.0 : ((lane > i) ? sM[i][lane] : 0.0);
            double dot = warp_sum(q * v);
            q -= tau * dot * v;
        }
        sQ[w][lane] = q;
    }
    __syncthreads();

    if (tid < CH) {
        const int c = tid;
        float tf  = decode_time(timep);
        float dt  = tf / 10.0f;
        float ddt = dt / 5.0f;
        float A[LCOLS];
        #pragma unroll
        for (int j = 0; j < LCOLS; j++) {
            float s = 0.0f;
            #pragma unroll
            for (int cc = 0; cc < NNULL; cc++)
                s += theta[c * NNULL + cc] * (float)sQ[cc][j];
            A[j] = s;
        }
        bool ok = true;
        #pragma unroll
        for (int k = 0; k < NCELL; k++) {
            float a = A[2 * k], b = A[2 * k + 1];
            float eta, gam;
            if (fabsf(a) > 1e-7f) {
                eta = expf(dt * a);
                gam = __fmul_rn(__fdiv_rn(b, a), __fsub_rn(eta, 1.0f));
            } else { eta = 1.0f; gam = __fmul_rn(b, dt); }
            float ex = __fadd_rn(1.0f, __fmul_rn(ddt, a));
            if (!(ex > 0.0f) || !(eta > 0.0f)) ok = false;
            g_eg[k * CH + c] = make_float2(eta, __fmul_rn(gam, 16.0f));
            g_eu[k * CH + c] = make_float2(ex,
                                           __fmul_rn(__fmul_rn(ddt, b), 16.0f));
        }
        if (!ok) g_flag = 0;
    }
}

// ---------------------------------------------------------------------------
__global__ void __launch_bounds__(512)
cpab_endpoints() {
    __shared__ float2 s_eg[NCELL * CH], s_eu[NCELL * CH];
    for (int i = threadIdx.x; i < NCELL * CH; i += blockDim.x) {
        s_eg[i] = g_eg[i]; s_eu[i] = g_eu[i];
    }
    __syncthreads();
    const int e = blockIdx.x * blockDim.x + threadIdx.x;
    if (e >= CH * (KB + 1)) return;
    const int c = e / (KB + 1);
    const int j = e - c * (KB + 1);
    g_ep[e] = cpab_eval((float)j * (1.0f / 256.0f), c, s_eg, s_eu);
}

// ---------------------------------------------------------------------------
__global__ void cpab_binbuild() {
    int b = blockIdx.x * blockDim.x + threadIdx.x;
    if (b >= CH * KB) return;
    int c = b >> 12, j = b & (KB - 1);
    EndPt L = g_ep[c * (KB + 1) + j];
    EndPt R = g_ep[c * (KB + 1) + j + 1];
    if (ep_agree(L, R) && g_flag != 0) {
        g_bins[b] = make_float2(L.m, L.t);
    } else {
        int idx = atomicAdd(&g_nref, 1);
        int payload = -1;
        if (idx < RCAP) { g_reflist[idx] = (c << 12) | j; payload = idx; }
        g_bins[b] = make_float2(__int_as_float(0x7fc00000),
                                __int_as_float(payload));
    }
}

// ---------------------------------------------------------------------------
__global__ void __launch_bounds__(512)
cpab_refine_eval() {
    const int nref = min(g_nref, RCAP);
    const long long total = (long long)nref * (NSUB + 1);
    const long long stride = (long long)gridDim.x * blockDim.x;
    for (long long t = (long long)blockIdx.x * blockDim.x + threadIdx.x;
         t < total; t += stride) {
        int r = (int)(t / (NSUB + 1));
        int s = (int)(t - (long long)r * (NSUB + 1));
        int cbv = g_reflist[r];
        int c = cbv >> 12, b = cbv & (KB - 1);
        g_ep2[r * (NSUB + 1) + s] =
            cpab_eval((float)(b * NSUB + s) * (1.0f / 2048.0f), c, g_eg, g_eu);
    }
}

__global__ void __launch_bounds__(512)
cpab_binbuild2() {
    const int nref = min(g_nref, RCAP);
    const long long total = (long long)nref * NSUB;
    const long long stride = (long long)gridDim.x * blockDim.x;
    const int flag = g_flag;
    for (long long t = (long long)blockIdx.x * blockDim.x + threadIdx.x;
         t < total; t += stride) {
        int r = (int)(t >> 3);
        int s = (int)(t & (NSUB - 1));
        EndPt L = g_ep2[r * (NSUB + 1) + s];
        EndPt R = g_ep2[r * (NSUB + 1) + s + 1];
        g_bins2[r * NSUB + s] =
            (ep_agree(L, R) && flag != 0)
                ? make_float2(L.m, L.t)
                : make_float2(__int_as_float(0x7fc00000), 0.0f);
    }
}

// ---------------------------------------------------------------------------
// Pass 1: float4, 4 independent 2-level lookup chains per thread.
// All per-lane state is manual scalars (macros) — no LMEM possible.
// ---------------------------------------------------------------------------
#define P1_PREP(J, XX)                                                        \
    float s##J = __fmaf_rn(XX, 1.0f / 6.0f, 0.5f);                            \
    bool ood##J = (s##J >= 1.0f) || (s##J <= 0.0f);                           \
    float q##J = ood##J ? 8.0f : __fmul_rn(s##J, 16.0f);                      \
    int bin##J = min((int)__fmul_rn(q##J, 256.0f), KB - 1);

#define P1_L2ADDR(J)                                                          \
    bool nan1_##J = !(mt##J.x == mt##J.x);                                    \
    int idx##J = __float_as_int(mt##J.y);                                     \
    int sub##J = min(max((int)__fmul_rn(q##J, 2048.0f) - (bin##J << 3), 0),   \
                     NSUB - 1);                                               \
    int a2_##J = (nan1_##J && idx##J >= 0) ? idx##J * NSUB + sub##J : 0;

#define P1_RESOLVE(J, XX, RR)                                                 \
    {                                                                         \
        float2 use = nan1_##J ? m2##J : mt##J;                                \
        bool bad = nan1_##J && (idx##J < 0 || !(m2##J.x == m2##J.x));         \
        if (ood##J) { RR = XX; }                                              \
        else if (!bad) {                                                      \
            RR = __fmaf_rn(__fmaf_rn(use.x, q##J, use.y), 0.375f, -3.0f);     \
        } else {                                                              \
            int pos = atomicAdd(&s_cnt, 1);                                   \
            if (pos < BUFCAP) { s_buf[pos] = (i4 << 2) + J; RR = 0.0f; }      \
            else RR = __fmaf_rn(cpab_iter(q##J, cb + J, g_eg, g_eu),          \
                                0.375f, -3.0f);                               \
        }                                                                     \
    }

__global__ void __launch_bounds__(512, 2)
cpab_pass1(const float4* __restrict__ x4, const float* __restrict__ x,
           const float* __restrict__ theta, float4* __restrict__ out4,
           float* __restrict__ out, int n4, long long n, int ntheta) {
    extern __shared__ int s_buf[];
    __shared__ int s_cnt, s_base;
    if (threadIdx.x == 0) s_cnt = 0;
    __syncthreads();

    const int stride = gridDim.x * blockDim.x;
    const int gtid = blockIdx.x * blockDim.x + threadIdx.x;

    for (int t = gtid; t < ntheta; t += stride)
        out[n + t] = theta[t];

    const int rem = (int)(n - (long long)n4 * 4);
    if (blockIdx.x == 0) {
        for (int t = threadIdx.x; t < rem; t += blockDim.x) {
            long long i = (long long)n4 * 4 + t;
            float xv = x[i];
            float s = __fmaf_rn(xv, 1.0f / 6.0f, 0.5f);
            if (s >= 1.0f || s <= 0.0f) { out[i] = xv; continue; }
            float r = cpab_iter(__fmul_rn(s, 16.0f), (int)(i & (CH - 1)),
                                g_eg, g_eu);
            out[i] = __fmaf_rn(r, 0.375f, -3.0f);
        }
    }

    for (int i4 = gtid; i4 < n4; i4 += stride) {
        const float4 xv = __ldg(x4 + i4);
        const int cb = (i4 << 2) & (CH - 1);

        P1_PREP(0, xv.x)  P1_PREP(1, xv.y)
        P1_PREP(2, xv.z)  P1_PREP(3, xv.w)

        // 4 level-1 gathers in flight
        const float2 mt0 = __ldg(&g_bins[((cb + 0) << 12) + bin0]);
        const float2 mt1 = __ldg(&g_bins[((cb + 1) << 12) + bin1]);
        const float2 mt2 = __ldg(&g_bins[((cb + 2) << 12) + bin2]);
        const float2 mt3 = __ldg(&g_bins[((cb + 3) << 12) + bin3]);

        P1_L2ADDR(0)  P1_L2ADDR(1)  P1_L2ADDR(2)  P1_L2ADDR(3)

        // 4 level-2 gathers in flight (addr 0 for valid lanes: 1 sector)
        const float2 m20 = __ldg(&g_bins2[a2_0]);
        const float2 m21 = __ldg(&g_bins2[a2_1]);
        const float2 m22 = __ldg(&g_bins2[a2_2]);
        const float2 m23 = __ldg(&g_bins2[a2_3]);

        float4 res;
        P1_RESOLVE(0, xv.x, res.x)  P1_RESOLVE(1, xv.y, res.y)
        P1_RESOLVE(2, xv.z, res.z)  P1_RESOLVE(3, xv.w, res.w)

        out4[i4] = res;
    }

    __syncthreads();
    int cnt = min(s_cnt, BUFCAP);
    if (threadIdx.x == 0) s_base = atomicAdd(&g_qcount, cnt);
    __syncthreads();
    int base = s_base;
    for (int k = threadIdx.x; k < cnt; k += blockDim.x)
        g_queue[base + k] = s_buf[k];
}

// ---------------------------------------------------------------------------
__global__ void __launch_bounds__(512, 3)
cpab_pass2(const float* __restrict__ x, float* __restrict__ out) {
    __shared__ float2 s_eg[NCELL * CH], s_eu[NCELL * CH];
    for (int i = threadIdx.x; i < NCELL * CH; i += blockDim.x) {
        s_eg[i] = g_eg[i]; s_eu[i] = g_eu[i];
    }
    __syncthreads();
    const int total = g_qcount;
    const int stride = gridDim.x * blockDim.x;
    for (int t = blockIdx.x * blockDim.x + threadIdx.x; t < total; t += stride) {
        int i = g_queue[t];
        float xv = __ldg(x + i);
        float s = __fmaf_rn(xv, 1.0f / 6.0f, 0.5f);
        float q = __fmul_rn(s, 16.0f);
        float r = cpab_iter(q, i & (CH - 1), s_eg, s_eu);
        out[i] = __fmaf_rn(r, 0.375f, -3.0f);
    }
}

extern "C" void kernel_launch(void* const* d_in, const int* in_sizes, int n_in,
                              void* d_out, int out_size) {
    const float* x     = (const float*)d_in[0];
    const void*  timep = d_in[4];
    const float* theta = (const float*)d_in[5];
    float* out = (float*)d_out;

    const long long n = (long long)in_sizes[0];
    const int ntheta = out_size - (int)n;
    const int n4 = (int)(n >> 2);

    cpab_setup<<<1, 512>>>(theta, timep);
    cpab_endpoints<<<(CH * (KB + 1) + 511) / 512, 512>>>();
    cpab_binbuild<<<(CH * KB) / 512, 512>>>();
    cpab_refine_eval<<<912, 512>>>();
    cpab_binbuild2<<<912, 512>>>();

    cudaFuncSetAttribute(cpab_pass1,
                         cudaFuncAttributeMaxDynamicSharedMemorySize,
                         BUFCAP * (int)sizeof(int));
    cpab_pass1<<<304, 512, BUFCAP * sizeof(int)>>>(
        (const float4*)x, x, theta, (float4*)out, out, n4, n, ntheta);
    cpab_pass2<<<304, 512>>>(x, out);
}

// round 13
// speedup vs baseline: 1.9347x; 1.0427x over previous
#include <cuda_runtime.h>
#include <math.h>

// CPABActivationDifferent: out[n][c] = cpab_transform(x[n][c]; theta[c]).
// Two-level piecewise-affine table + compacted iterative fallback.
// B_BASIS: dgesdd N>>M path => rows 17..31 of Vt come from the LQ
// factorization (dgelq2+dorgl2), reimplemented in fp64.
//
// R13 (= R12 resubmit after infra failure, audited): pass1 is channel-
// blocked — each block owns 4 consecutive channels and caches their full
// level-1 tables (128KB) in SMEM, converting the fully divergent L2 gather
// (measured ~2 cyc/elem of L1tex replays, the R10/R11 bottleneck) into a
// ~0.2 cyc/elem LDS. x/out are accessed strided (1KB channel stride),
// costing 2x sector traffic — a good trade.

#define NCELL 16
#define CH 256
#define LROWS 17
#define LCOLS 32
#define NNULL 15
#define KB 4096
#define NSUB 8
#define RCAP (1 << 19)
#define QUEUE_CAP (1 << 25)
#define P1BUF 8192            // per-block queue staging in pass1 (32KB)
#define CPB 4                 // channels per block
#define RSPLIT 7              // row splits
#define FNV_P 1099511628211ull
#define FULLM 0xffffffffu

__device__ float2 g_eg[NCELL * CH];   // (eta, 16*gamma)
__device__ float2 g_eu[NCELL * CH];   // (1+ddt*a, 16*ddt*b)
__device__ int    g_flag, g_qcount, g_nref;
struct EndPt { float m, t; unsigned long long h; };
__device__ EndPt  g_ep[CH * (KB + 1)];
__device__ EndPt  g_ep2[RCAP * (NSUB + 1)];
__device__ float2 g_bins[CH * KB];        // valid:(m,t)  invalid:(NaN, idx|-1)
__device__ int    g_reflist[RCAP];        // packed (c<<12)|bin
__device__ float2 g_bins2[RCAP * NSUB];   // refined sub-bins
__device__ int    g_queue[QUEUE_CAP];

__device__ __forceinline__ float decode_time(const void* tptr) {
    int iv = *(const int*)tptr;
    float fv = __int_as_float(iv);
    float af = fabsf(fv);
    if (af >= 1e-6f && af <= 1e6f) return fv;
    return (float)iv;
}
__device__ __forceinline__ double warp_sum(double v) {
    #pragma unroll
    for (int off = 16; off; off >>= 1)
        v += __shfl_xor_sync(FULLM, v, off);
    return v;
}
__device__ __forceinline__ int cell16(float q) { return min((int)q, 15); }

// Exact iterative engine (identical arithmetic to the passing R6 kernel).
__device__ __forceinline__ float cpab_iter(float q, int c,
                                           const float2* __restrict__ eg,
                                           const float2* __restrict__ eu) {
    #pragma unroll 1
    for (int st = 0; st < 10; ++st) {
        int c0 = cell16(q);
        float2 g = eg[(c0 << 8) + c];
        float2 u = eu[(c0 << 8) + c];
        float qc = __fmaf_rn(g.x, q, g.y);
        float qe = __fmaf_rn(u.x, q, u.y);
        #pragma unroll
        for (int ss = 1; ss < 5; ++ss) {
            int cc = cell16(qe);
            float2 v = eu[(cc << 8) + c];
            qe = __fmaf_rn(v.x, qe, v.y);
        }
        q = (cell16(qc) == c0) ? qc : qe;
    }
    return q;
}

// Endpoint evaluation: decision-path hash + composed affine (m,t).
__device__ __forceinline__ EndPt cpab_eval(float q, int c,
                                           const float2* __restrict__ eg,
                                           const float2* __restrict__ eu) {
    unsigned long long h = 1469598103934665603ull;
    float m = 1.0f, t = 0.0f;
    #pragma unroll 1
    for (int st = 0; st < 10; ++st) {
        int c0 = cell16(q);
        float2 g = eg[(c0 << 8) + c];
        float2 u = eu[(c0 << 8) + c];
        float qc = __fmaf_rn(g.x, q, g.y);
        float qe = __fmaf_rn(u.x, q, u.y);
        float A = u.x, B = u.y;
        int cc[4];
        #pragma unroll
        for (int ss = 0; ss < 4; ++ss) {
            cc[ss] = cell16(qe);
            float2 v = eu[(cc[ss] << 8) + c];
            qe = __fmaf_rn(v.x, qe, v.y);
            A  = __fmul_rn(v.x, A);
            B  = __fmaf_rn(v.x, B, v.y);
        }
        int c1 = cell16(qc);
        bool stay = (c1 == c0);
        h = (h ^ (unsigned long long)c0) * FNV_P;
        h = (h ^ (unsigned long long)(c1 + 16)) * FNV_P;
        float am, bm;
        if (stay) { am = g.x; bm = g.y; q = qc; }
        else {
            #pragma unroll
            for (int ss = 0; ss < 4; ++ss)
                h = (h ^ (unsigned long long)(cc[ss] + 32 + 16 * ss)) * FNV_P;
            am = A; bm = B; q = qe;
        }
        m = __fmul_rn(am, m);
        t = __fmaf_rn(am, t, bm);
    }
    EndPt e; e.m = m; e.t = t; e.h = h; return e;
}

__device__ __forceinline__ bool ep_agree(const EndPt& L, const EndPt& R) {
    return (L.h == R.h) &&
           (__float_as_int(L.m) == __float_as_int(R.m)) &&
           (__float_as_int(L.t) == __float_as_int(R.t)) &&
           (L.m > 0.0f);
}

// ---------------------------------------------------------------------------
__global__ void cpab_setup(const float* __restrict__ theta,
                           const void*  __restrict__ timep) {
    __shared__ double sM[LROWS][LCOLS];
    __shared__ double stau[LROWS];
    __shared__ double sQ[NNULL][LCOLS];
    const int tid = threadIdx.x, lane = tid & 31, w = tid >> 5;

    if (tid == 0) { g_qcount = 0; g_nref = 0; g_flag = 1; }

    for (int i = tid; i < LROWS * LCOLS; i += blockDim.x)
        ((double*)sM)[i] = 0.0;
    __syncthreads();
    if (tid == 0) {
        for (int k = 1; k < NCELL; k++) {
            double xk = (double)k / (double)NCELL;
            sM[k - 1][2 * (k - 1)]     =  xk;
            sM[k - 1][2 * (k - 1) + 1] =  1.0;
            sM[k - 1][2 * k]           = -xk;
            sM[k - 1][2 * k + 1]       = -1.0;
        }
        sM[NCELL - 1][1] = 1.0;
        sM[NCELL][2 * NCELL - 2] = 1.0;
        sM[NCELL][2 * NCELL - 1] = 1.0;
    }
    __syncthreads();

    for (int i = 0; i < LROWS; i++) {
        if (w == 0) {
            double aij = sM[i][lane];
            double sq  = (lane > i) ? aij * aij : 0.0;
            sq = warp_sum(sq);
            double alpha = __shfl_sync(FULLM, aij, i);
            double xnorm = sqrt(sq);
            double tau = 0.0;
            if (xnorm != 0.0) {
                double aa = fabs(alpha);
                double wv = fmax(aa, xnorm), zv = fmin(aa, xnorm);
                double r  = (zv == 0.0) ? wv
                            : wv * sqrt(1.0 + (zv / wv) * (zv / wv));
                double beta = (alpha >= 0.0) ? -r : r;
                tau = (beta - alpha) / beta;
                double inv = 1.0 / (alpha - beta);
                if (lane > i)  sM[i][lane] = aij * inv;
                if (lane == i) sM[i][i] = beta;
            }
            if (lane == 0) stau[i] = tau;
        }
        __syncthreads();
        int r = i + 1 + w;
        if (r < LROWS) {
            double tau = stau[i];
            if (tau != 0.0) {
                double v   = (lane == i) ? 1.0
                             : ((lane > i) ? sM[i][lane] : 0.0);
                double arj = (lane >= i) ? sM[r][lane] : 0.0;
                double dot = warp_sum(arj * v);
                if (lane >= i) sM[r][lane] = arj - tau * dot * v;
            }
        }
        __syncthreads();
    }
    if (w < NNULL) {
        int r = LROWS + w;
        double q = (lane == r) ? 1.0 : 0.0;
        for (int i = LROWS - 1; i >= 0; i--) {
            double tau = stau[i];
            double v = (lane == i) ? 1.0 : ((lane > i) ? sM[i][lane] : 0.0);
            double dot = warp_sum(q * v);
            q -= tau * dot * v;
        }
        sQ[w][lane] = q;
    }
    __syncthreads();

    if (tid < CH) {
        const int c = tid;
        float tf  = decode_time(timep);
        float dt  = tf / 10.0f;
        float ddt = dt / 5.0f;
        float A[LCOLS];
        #pragma unroll
        for (int j = 0; j < LCOLS; j++) {
            float s = 0.0f;
            #pragma unroll
            for (int cc = 0; cc < NNULL; cc++)
                s += theta[c * NNULL + cc] * (float)sQ[cc][j];
            A[j] = s;
        }
        bool ok = true;
        #pragma unroll
        for (int k = 0; k < NCELL; k++) {
            float a = A[2 * k], b = A[2 * k + 1];
            float eta, gam;
            if (fabsf(a) > 1e-7f) {
                eta = expf(dt * a);
                gam = __fmul_rn(__fdiv_rn(b, a), __fsub_rn(eta, 1.0f));
            } else { eta = 1.0f; gam = __fmul_rn(b, dt); }
            float ex = __fadd_rn(1.0f, __fmul_rn(ddt, a));
            if (!(ex > 0.0f) || !(eta > 0.0f)) ok = false;
            g_eg[k * CH + c] = make_float2(eta, __fmul_rn(gam, 16.0f));
            g_eu[k * CH + c] = make_float2(ex,
                                           __fmul_rn(__fmul_rn(ddt, b), 16.0f));
        }
        if (!ok) g_flag = 0;
    }
}

// ---------------------------------------------------------------------------
__global__ void __launch_bounds__(512)
cpab_endpoints() {
    __shared__ float2 s_eg[NCELL * CH], s_eu[NCELL * CH];
    for (int i = threadIdx.x; i < NCELL * CH; i += blockDim.x) {
        s_eg[i] = g_eg[i]; s_eu[i] = g_eu[i];
    }
    __syncthreads();
    const int e = blockIdx.x * blockDim.x + threadIdx.x;
    if (e >= CH * (KB + 1)) return;
    const int c = e / (KB + 1);
    const int j = e - c * (KB + 1);
    g_ep[e] = cpab_eval((float)j * (1.0f / 256.0f), c, s_eg, s_eu);
}

// ---------------------------------------------------------------------------
__global__ void cpab_binbuild() {
    int b = blockIdx.x * blockDim.x + threadIdx.x;
    if (b >= CH * KB) return;
    int c = b >> 12, j = b & (KB - 1);
    EndPt L = g_ep[c * (KB + 1) + j];
    EndPt R = g_ep[c * (KB + 1) + j + 1];
    if (ep_agree(L, R) && g_flag != 0) {
        g_bins[b] = make_float2(L.m, L.t);
    } else {
        int idx = atomicAdd(&g_nref, 1);
        int payload = -1;
        if (idx < RCAP) { g_reflist[idx] = (c << 12) | j; payload = idx; }
        g_bins[b] = make_float2(__int_as_float(0x7fc00000),
                                __int_as_float(payload));
    }
}

// ---------------------------------------------------------------------------
__global__ void __launch_bounds__(512)
cpab_refine_eval() {
    const int nref = min(g_nref, RCAP);
    const long long total = (long long)nref * (NSUB + 1);
    const long long stride = (long long)gridDim.x * blockDim.x;
    for (long long t = (long long)blockIdx.x * blockDim.x + threadIdx.x;
         t < total; t += stride) {
        int r = (int)(t / (NSUB + 1));
        int s = (int)(t - (long long)r * (NSUB + 1));
        int cbv = g_reflist[r];
        int c = cbv >> 12, b = cbv & (KB - 1);
        g_ep2[r * (NSUB + 1) + s] =
            cpab_eval((float)(b * NSUB + s) * (1.0f / 2048.0f), c, g_eg, g_eu);
    }
}

__global__ void __launch_bounds__(512)
cpab_binbuild2() {
    const int nref = min(g_nref, RCAP);
    const long long total = (long long)nref * NSUB;
    const long long stride = (long long)gridDim.x * blockDim.x;
    const int flag = g_flag;
    for (long long t = (long long)blockIdx.x * blockDim.x + threadIdx.x;
         t < total; t += stride) {
        int r = (int)(t >> 3);
        int s = (int)(t & (NSUB - 1));
        EndPt L = g_ep2[r * (NSUB + 1) + s];
        EndPt R = g_ep2[r * (NSUB + 1) + s + 1];
        g_bins2[r * NSUB + s] =
            (ep_agree(L, R) && flag != 0)
                ? make_float2(L.m, L.t)
                : make_float2(__int_as_float(0x7fc00000), 0.0f);
    }
}

// ---------------------------------------------------------------------------
// Pass 1 (channel-blocked): block = (channel group of 4, row split).
// Level-1 table for the 4 channels lives in SMEM; gather = LDS.64.
// ---------------------------------------------------------------------------
#define P1_PREP(J, XX)                                                        \
    float s##J = __fmaf_rn(XX, 1.0f / 6.0f, 0.5f);                            \
    bool ood##J = (s##J >= 1.0f) || (s##J <= 0.0f);                           \
    float q##J = ood##J ? 8.0f : __fmul_rn(s##J, 16.0f);                      \
    int bin##J = min((int)__fmul_rn(q##J, 256.0f), KB - 1);

#define P1_L2ADDR(J)                                                          \
    bool nan1_##J = !(mt##J.x == mt##J.x);                                    \
    int idx##J = __float_as_int(mt##J.y);                                     \
    int sub##J = min(max((int)__fmul_rn(q##J, 2048.0f) - (bin##J << 3), 0),   \
                     NSUB - 1);                                               \
    int a2_##J = (nan1_##J && idx##J >= 0) ? idx##J * NSUB + sub##J : 0;

#define P1_RESOLVE(J, XX, RR)                                                 \
    {                                                                         \
        float2 use = nan1_##J ? m2##J : mt##J;                                \
        bool bad = nan1_##J && (idx##J < 0 || !(m2##J.x == m2##J.x));         \
        if (ood##J) { RR = XX; }                                              \
        else if (!bad) {                                                      \
            RR = __fmaf_rn(__fmaf_rn(use.x, q##J, use.y), 0.375f, -3.0f);     \
        } else {                                                              \
            int pos = atomicAdd(&s_cnt, 1);                                   \
            if (pos < P1BUF) { s_buf[pos] = ebase + J; RR = 0.0f; }           \
            else RR = __fmaf_rn(cpab_iter(q##J, cb + J, g_eg, g_eu),          \
                                0.375f, -3.0f);                               \
        }                                                                     \
    }

__global__ void __launch_bounds__(1024, 1)
cpab_pass1(const float4* __restrict__ x4, const float* __restrict__ x,
           const float* __restrict__ theta, float4* __restrict__ out4,
           float* __restrict__ out, int rows, int rpb,
           long long n, int ntheta) {
    extern __shared__ char smraw[];
    float2* s_tab = (float2*)smraw;                         // 4*4096*8 =128KB
    int* s_buf = (int*)(smraw + CPB * KB * sizeof(float2)); // 32KB
    __shared__ int s_cnt, s_base;

    const int grp = blockIdx.x & 63;            // channel group (4 channels)
    const int rsp = blockIdx.x >> 6;            // row split
    const int cb  = grp << 2;

    // Stage the 4 channels' level-1 tables (contiguous slabs) into SMEM.
    {
        const float4* src = (const float4*)(g_bins + ((size_t)cb << 12));
        float4* dst = (float4*)s_tab;
        for (int i = threadIdx.x; i < CPB * KB / 2; i += blockDim.x)
            dst[i] = __ldg(src + i);
    }
    if (threadIdx.x == 0) s_cnt = 0;
    __syncthreads();

    // theta passthrough: row-split-0 blocks cover it (64*1024 >= ntheta)
    if (rsp == 0) {
        for (int t = grp * (int)blockDim.x + (int)threadIdx.x; t < ntheta;
             t += 64 * (int)blockDim.x)
            out[n + t] = theta[t];
    }
    // scalar tail (n % 256 != 0): block 0 via exact engine
    if (blockIdx.x == 0) {
        const long long nfull = (long long)rows * CH;
        for (long long i = nfull + threadIdx.x; i < n; i += blockDim.x) {
            float xv = x[i];
            float s = __fmaf_rn(xv, 1.0f / 6.0f, 0.5f);
            if (s >= 1.0f || s <= 0.0f) { out[i] = xv; continue; }
            float r = cpab_iter(__fmul_rn(s, 16.0f), (int)(i & (CH - 1)),
                                g_eg, g_eu);
            out[i] = __fmaf_rn(r, 0.375f, -3.0f);
        }
    }

    const int r0 = rsp * rpb;
    const int r1 = min(rows, r0 + rpb);

    int r = r0 + (int)threadIdx.x;
    float4 xv = (r < r1) ? __ldg(x4 + ((size_t)r << 6) + grp)
                         : make_float4(9e9f, 9e9f, 9e9f, 9e9f);
    while (r < r1) {
        const int rn = r + (int)blockDim.x;
        float4 xnext = (rn < r1) ? __ldg(x4 + ((size_t)rn << 6) + grp)
                                 : make_float4(9e9f, 9e9f, 9e9f, 9e9f);
        const int ebase = (r << 8) + cb;        // element index; n < 2^31

        P1_PREP(0, xv.x)  P1_PREP(1, xv.y)
        P1_PREP(2, xv.z)  P1_PREP(3, xv.w)

        // 4 SMEM gathers (LDS.64, random-bank ~4-way)
        const float2 mt0 = s_tab[(0 << 12) + bin0];
        const float2 mt1 = s_tab[(1 << 12) + bin1];
        const float2 mt2 = s_tab[(2 << 12) + bin2];
        const float2 mt3 = s_tab[(3 << 12) + bin3];

        P1_L2ADDR(0)  P1_L2ADDR(1)  P1_L2ADDR(2)  P1_L2ADDR(3)

        // level-2 gathers (global; addr 0 broadcast for valid lanes)
        const float2 m20 = __ldg(&g_bins2[a2_0]);
        const float2 m21 = __ldg(&g_bins2[a2_1]);
        const float2 m22 = __ldg(&g_bins2[a2_2]);
        const float2 m23 = __ldg(&g_bins2[a2_3]);

        float4 res;
        P1_RESOLVE(0, xv.x, res.x)  P1_RESOLVE(1, xv.y, res.y)
        P1_RESOLVE(2, xv.z, res.z)  P1_RESOLVE(3, xv.w, res.w)

        out4[((size_t)r << 6) + grp] = res;
        r = rn;
        xv = xnext;
    }

    __syncthreads();
    int cnt = min(s_cnt, P1BUF);
    if (threadIdx.x == 0) s_base = atomicAdd(&g_qcount, cnt);
    __syncthreads();
    int qb = s_base;
    for (int k = (int)threadIdx.x; k < cnt; k += (int)blockDim.x)
        if (qb + k < QUEUE_CAP) g_queue[qb + k] = s_buf[k];
}

// ---------------------------------------------------------------------------
__global__ void __launch_bounds__(512, 3)
cpab_pass2(const float* __restrict__ x, float* __restrict__ out) {
    __shared__ float2 s_eg[NCELL * CH], s_eu[NCELL * CH];
    for (int i = threadIdx.x; i < NCELL * CH; i += blockDim.x) {
        s_eg[i] = g_eg[i]; s_eu[i] = g_eu[i];
    }
    __syncthreads();
    const int total = min(g_qcount, QUEUE_CAP);
    const int stride = gridDim.x * blockDim.x;
    for (int t = blockIdx.x * blockDim.x + threadIdx.x; t < total; t += stride) {
        int i = g_queue[t];
        float xv = __ldg(x + i);
        float s = __fmaf_rn(xv, 1.0f / 6.0f, 0.5f);
        float q = __fmul_rn(s, 16.0f);
        float r = cpab_iter(q, i & (CH - 1), s_eg, s_eu);
        out[i] = __fmaf_rn(r, 0.375f, -3.0f);
    }
}

extern "C" void kernel_launch(void* const* d_in, const int* in_sizes, int n_in,
                              void* d_out, int out_size) {
    const float* x     = (const float*)d_in[0];
    const void*  timep = d_in[4];
    const float* theta = (const float*)d_in[5];
    float* out = (float*)d_out;

    const long long n = (long long)in_sizes[0];
    const int ntheta = out_size - (int)n;
    const int rows = (int)(n >> 8);              // full rows of 256 channels
    const int rpb  = (rows + RSPLIT - 1) / RSPLIT > 0
                     ? (rows + RSPLIT - 1) / RSPLIT : 1;

    cpab_setup<<<1, 512>>>(theta, timep);
    cpab_endpoints<<<(CH * (KB + 1) + 511) / 512, 512>>>();
    cpab_binbuild<<<(CH * KB) / 512, 512>>>();
    cpab_refine_eval<<<912, 512>>>();
    cpab_binbuild2<<<912, 512>>>();

    const int p1smem = CPB * KB * (int)sizeof(float2) + P1BUF * (int)sizeof(int);
    // Immediate (non-stream) API; idempotent, safe under graph capture.
    cudaFuncSetAttribute(cpab_pass1,
                         cudaFuncAttributeMaxDynamicSharedMemorySize, p1smem);

    cpab_pass1<<<64 * RSPLIT, 1024, p1smem>>>(
        (const float4*)x, x, theta, (float4*)out, out, rows, rpb, n, ntheta);
    cpab_pass2<<<304, 512>>>(x, out);
}